// round 1
// baseline (speedup 1.0000x reference)
#include <cuda_runtime.h>
#include <math.h>

#define BB 2
#define NH 16
#define TT 2048
#define DD 64
#define EE 1024
#define SRC 128

// Scratch for projected Q/K/V in [B, H, T, D] layout (no cudaMalloc allowed).
__device__ float g_q[BB * NH * TT * DD];
__device__ float g_k[BB * NH * TT * DD];
__device__ float g_v[BB * NH * TT * DD];

// ---------------------------------------------------------------------------
// QKV projection: y = x @ W^T + b, scattered into [B, H, T, D].
// Block tile 64x64, K-step 16, 256 threads, 4x4 micro-tile per thread.
// grid = (N/64=16, M/64=64, 3); z selects Q/K/V.
// ---------------------------------------------------------------------------
__global__ __launch_bounds__(256) void qkv_gemm_kernel(
    const float* __restrict__ x,
    const float* __restrict__ Wq, const float* __restrict__ bq,
    const float* __restrict__ Wk, const float* __restrict__ bk,
    const float* __restrict__ Wv, const float* __restrict__ bv)
{
    __shared__ float As[16][64];
    __shared__ float Bs[16][64];

    const int z = blockIdx.z;
    const float* __restrict__ W    = (z == 0) ? Wq : (z == 1) ? Wk : Wv;
    const float* __restrict__ bias = (z == 0) ? bq : (z == 1) ? bk : bv;
    float* __restrict__ dst        = (z == 0) ? g_q : (z == 1) ? g_k : g_v;

    const int m0 = blockIdx.y * 64;
    const int n0 = blockIdx.x * 64;
    const int tid = threadIdx.x;
    const int ty = tid >> 4;        // 0..15
    const int tx = tid & 15;        // 0..15
    const int lr = tid >> 2;        // 0..63 : row for cooperative loads
    const int lk = (tid & 3) * 4;   // 0,4,8,12 : k offset (float4)

    float acc[4][4] = {};

    for (int k0 = 0; k0 < EE; k0 += 16) {
        float4 av = *(const float4*)&x[(size_t)(m0 + lr) * EE + k0 + lk];
        float4 bv4 = *(const float4*)&W[(size_t)(n0 + lr) * EE + k0 + lk];
        __syncthreads();
        As[lk + 0][lr] = av.x;  As[lk + 1][lr] = av.y;
        As[lk + 2][lr] = av.z;  As[lk + 3][lr] = av.w;
        Bs[lk + 0][lr] = bv4.x; Bs[lk + 1][lr] = bv4.y;
        Bs[lk + 2][lr] = bv4.z; Bs[lk + 3][lr] = bv4.w;
        __syncthreads();
        #pragma unroll
        for (int kk = 0; kk < 16; kk++) {
            float a[4], b[4];
            *(float4*)a = *(const float4*)&As[kk][ty * 4];
            *(float4*)b = *(const float4*)&Bs[kk][tx * 4];
            #pragma unroll
            for (int i = 0; i < 4; i++)
                #pragma unroll
                for (int j = 0; j < 4; j++)
                    acc[i][j] += a[i] * b[j];
        }
    }

    #pragma unroll
    for (int i = 0; i < 4; i++) {
        int n = m0 + ty * 4 + i;          // flattened (b, t)
        int bb = n >> 11;                 // /2048
        int t  = n & (TT - 1);
        #pragma unroll
        for (int j = 0; j < 4; j++) {
            int o = n0 + tx * 4 + j;      // h*64 + d
            int h = o >> 6;
            int d = o & 63;
            dst[(((size_t)(bb * NH + h) * TT) + t) * DD + d] = acc[i][j] + bias[o];
        }
    }
}

// ---------------------------------------------------------------------------
// Flash attention with prefix-causal band (key j valid iff j <= i + SRC).
// One block = (b, h, 64-query tile). 256 threads; 4x4 micro-tiles.
// Shared layout (floats):
//   Qst [64][64]  (transposed: [d][q]), Q pre-scaled by 1/8
//   Kst [64][64]  (transposed: [d][k])
//   Vs  [64][64]  ([k][d])
//   Ps  [64][65]  (scores / probabilities, padded)
//   mrow[64], lrow[64], arow[64], red[64][4]
// ---------------------------------------------------------------------------
#define SM_QST 0
#define SM_KST 4096
#define SM_VS  8192
#define SM_PS  12288
#define SM_M   (12288 + 64 * 65)     // 16448
#define SM_L   (SM_M + 64)
#define SM_A   (SM_L + 64)
#define SM_RED (SM_A + 64)
#define SM_TOTAL_FLOATS (SM_RED + 256)   // 16896 floats = 67584 bytes

__global__ __launch_bounds__(256) void attn_kernel(float* __restrict__ out)
{
    extern __shared__ float sm[];
    float* Qst = sm + SM_QST;
    float* Kst = sm + SM_KST;
    float* Vs  = sm + SM_VS;
    float* Ps  = sm + SM_PS;
    float* mrow = sm + SM_M;
    float* lrow = sm + SM_L;
    float* arow = sm + SM_A;
    float* red  = sm + SM_RED;

    const int qtile = gridDim.x - 1 - blockIdx.x;  // heavy tiles first
    const int h = blockIdx.y;
    const int b = blockIdx.z;
    const int qs = qtile * 64;

    const float* __restrict__ Qb = g_q + (size_t)(b * NH + h) * TT * DD;
    const float* __restrict__ Kb = g_k + (size_t)(b * NH + h) * TT * DD;
    const float* __restrict__ Vb = g_v + (size_t)(b * NH + h) * TT * DD;

    const int tid = threadIdx.x;
    const int ty = tid >> 4;       // 0..15
    const int tx = tid & 15;       // 0..15
    const int lr  = tid >> 2;      // 0..63
    const int ld0 = (tid & 3) * 16;

    // Load Q tile transposed, pre-scaled by HEAD_DIM^-0.5 = 0.125
    #pragma unroll
    for (int e = 0; e < 16; e += 4) {
        float4 v = *(const float4*)&Qb[(size_t)(qs + lr) * DD + ld0 + e];
        Qst[(ld0 + e + 0) * 64 + lr] = v.x * 0.125f;
        Qst[(ld0 + e + 1) * 64 + lr] = v.y * 0.125f;
        Qst[(ld0 + e + 2) * 64 + lr] = v.z * 0.125f;
        Qst[(ld0 + e + 3) * 64 + lr] = v.w * 0.125f;
    }
    if (tid < 64) { mrow[tid] = -1e30f; lrow[tid] = 0.0f; }

    float O[4][4] = {};

    const int ntiles = min(TT / 64, qtile + 3);

    for (int jt = 0; jt < ntiles; jt++) {
        const int ks = jt * 64;
        __syncthreads();  // protect prev-iter reads of Vs/Ps/arow (and Q load, iter 0)

        // Load K (transposed) and V tiles
        #pragma unroll
        for (int e = 0; e < 16; e += 4) {
            float4 kv = *(const float4*)&Kb[(size_t)(ks + lr) * DD + ld0 + e];
            Kst[(ld0 + e + 0) * 64 + lr] = kv.x;
            Kst[(ld0 + e + 1) * 64 + lr] = kv.y;
            Kst[(ld0 + e + 2) * 64 + lr] = kv.z;
            Kst[(ld0 + e + 3) * 64 + lr] = kv.w;
            float4 vv = *(const float4*)&Vb[(size_t)(ks + lr) * DD + ld0 + e];
            *(float4*)&Vs[lr * 64 + ld0 + e] = vv;
        }
        __syncthreads();

        // S = (scaled Q) @ K^T, 4x4 per thread
        float s[4][4] = {};
        #pragma unroll 8
        for (int d = 0; d < 64; d++) {
            float a[4], k4[4];
            *(float4*)a  = *(const float4*)&Qst[d * 64 + ty * 4];
            *(float4*)k4 = *(const float4*)&Kst[d * 64 + tx * 4];
            #pragma unroll
            for (int i = 0; i < 4; i++)
                #pragma unroll
                for (int j = 0; j < 4; j++)
                    s[i][j] += a[i] * k4[j];
        }

        // Mask (only last band tile can be partially masked) + stage into Ps
        const bool need_mask = (ks + 63) > (qs + SRC);
        #pragma unroll
        for (int i = 0; i < 4; i++) {
            #pragma unroll
            for (int j = 0; j < 4; j++) {
                float val = s[i][j];
                if (need_mask && (ks + tx * 4 + j) > (qs + ty * 4 + i) + SRC)
                    val = -1e30f;
                Ps[(ty * 4 + i) * 65 + tx * 4 + j] = val;
            }
        }
        __syncthreads();

        // Row max (4 threads per row, 16 cols each)
        {
            const int r = tid >> 2, p = tid & 3;
            float mx = -1e30f;
            #pragma unroll 4
            for (int c = 0; c < 16; c++)
                mx = fmaxf(mx, Ps[r * 65 + p * 16 + c]);
            red[r * 4 + p] = mx;
        }
        __syncthreads();
        if (tid < 64) {
            float mt = fmaxf(fmaxf(red[tid * 4 + 0], red[tid * 4 + 1]),
                             fmaxf(red[tid * 4 + 2], red[tid * 4 + 3]));
            float mo = mrow[tid];
            float mn = fmaxf(mo, mt);
            arow[tid] = __expf(mo - mn);
            mrow[tid] = mn;
        }
        __syncthreads();

        // exp + partial row sums
        {
            const int r = tid >> 2, p = tid & 3;
            const float mn = mrow[r];
            float sum = 0.0f;
            #pragma unroll 4
            for (int c = 0; c < 16; c++) {
                float pv = __expf(Ps[r * 65 + p * 16 + c] - mn);
                Ps[r * 65 + p * 16 + c] = pv;
                sum += pv;
            }
            red[r * 4 + p] = sum;
        }
        __syncthreads();
        if (tid < 64) {
            lrow[tid] = lrow[tid] * arow[tid] +
                        (red[tid * 4 + 0] + red[tid * 4 + 1] +
                         red[tid * 4 + 2] + red[tid * 4 + 3]);
        }

        // Rescale O and accumulate P @ V
        float ai[4];
        #pragma unroll
        for (int i = 0; i < 4; i++) ai[i] = arow[ty * 4 + i];
        #pragma unroll
        for (int i = 0; i < 4; i++)
            #pragma unroll
            for (int j = 0; j < 4; j++)
                O[i][j] *= ai[i];

        #pragma unroll 8
        for (int k = 0; k < 64; k++) {
            float p4[4], v4[4];
            #pragma unroll
            for (int i = 0; i < 4; i++) p4[i] = Ps[(ty * 4 + i) * 65 + k];
            *(float4*)v4 = *(const float4*)&Vs[k * 64 + tx * 4];
            #pragma unroll
            for (int i = 0; i < 4; i++)
                #pragma unroll
                for (int j = 0; j < 4; j++)
                    O[i][j] += p4[i] * v4[j];
        }
    }
    __syncthreads();  // lrow final values visible to all threads

    float linv[4];
    #pragma unroll
    for (int i = 0; i < 4; i++) linv[i] = 1.0f / lrow[ty * 4 + i];

    #pragma unroll
    for (int i = 0; i < 4; i++) {
        const int t = qs + ty * 4 + i;
        float* orow = out + ((size_t)(b * TT + t)) * EE + h * DD + tx * 4;
        #pragma unroll
        for (int j = 0; j < 4; j++)
            orow[j] = O[i][j] * linv[i];
    }
}

// ---------------------------------------------------------------------------
extern "C" void kernel_launch(void* const* d_in, const int* in_sizes, int n_in,
                              void* d_out, int out_size)
{
    (void)in_sizes; (void)n_in; (void)out_size;
    const float* x  = (const float*)d_in[0];
    const float* Wq = (const float*)d_in[1];
    const float* bq = (const float*)d_in[2];
    const float* Wk = (const float*)d_in[3];
    const float* bk = (const float*)d_in[4];
    const float* Wv = (const float*)d_in[5];
    const float* bv = (const float*)d_in[6];
    float* out = (float*)d_out;

    static const size_t attn_smem = SM_TOTAL_FLOATS * sizeof(float);
    cudaFuncSetAttribute(attn_kernel,
                         cudaFuncAttributeMaxDynamicSharedMemorySize,
                         (int)attn_smem);

    dim3 ggrid(EE / 64, (BB * TT) / 64, 3);
    qkv_gemm_kernel<<<ggrid, 256>>>(x, Wq, bq, Wk, bk, Wv, bv);

    dim3 agrid(TT / 64, NH, BB);
    attn_kernel<<<agrid, 256, attn_smem>>>(out);
}

// round 3
// speedup vs baseline: 2.3924x; 2.3924x over previous
#include <cuda_runtime.h>
#include <math.h>
#include <cstdint>

#define BB 2
#define NH 16
#define TT 2048
#define DD 64
#define EE 1024
#define SRC 128

// Scratch for projected Q/K/V in [B, H, T, D] layout (no cudaMalloc allowed).
__device__ float g_q[BB * NH * TT * DD];
__device__ float g_k[BB * NH * TT * DD];
__device__ float g_v[BB * NH * TT * DD];

__device__ __forceinline__ float to_tf32(float f) {
    float r;
    asm("cvt.rna.tf32.f32 %0, %1;" : "=f"(r) : "f"(f));
    return r;
}

// D += A(16x8) * B(8x8), tf32 inputs (as b32 regs), fp32 accum.
__device__ __forceinline__ void mma_tf32(
    float* d, uint32_t a0, uint32_t a1, uint32_t a2, uint32_t a3,
    uint32_t b0, uint32_t b1)
{
    asm volatile(
        "mma.sync.aligned.m16n8k8.row.col.f32.tf32.tf32.f32 "
        "{%0,%1,%2,%3}, {%4,%5,%6,%7}, {%8,%9}, {%0,%1,%2,%3};"
        : "+f"(d[0]), "+f"(d[1]), "+f"(d[2]), "+f"(d[3])
        : "r"(a0), "r"(a1), "r"(a2), "r"(a3), "r"(b0), "r"(b1));
}

// ===========================================================================
// QKV projection: y = x @ W^T + b, scattered into [B,H,T,D].  tf32 mma.sync.
// Block tile 128x128, 256 threads (8 warps as 4Mx2N; warp tile 32x64).
// K chunks of 32 floats staged in smem (pitch 36 -> conflict-free frags).
// grid = (8, 32, 3)
// ===========================================================================
#define GPITCH 36

__global__ __launch_bounds__(256) void qkv_gemm_tc(
    const float* __restrict__ x,
    const float* __restrict__ Wq, const float* __restrict__ bq,
    const float* __restrict__ Wk, const float* __restrict__ bk,
    const float* __restrict__ Wv, const float* __restrict__ bv)
{
    __shared__ float As[128 * GPITCH];
    __shared__ float Bs[128 * GPITCH];

    const int z = blockIdx.z;
    const float* __restrict__ W    = (z == 0) ? Wq : (z == 1) ? Wk : Wv;
    const float* __restrict__ bias = (z == 0) ? bq : (z == 1) ? bk : bv;
    float* __restrict__ dst        = (z == 0) ? g_q : (z == 1) ? g_k : g_v;

    const int m0 = blockIdx.y * 128;
    const int n0 = blockIdx.x * 128;
    const int tid = threadIdx.x;
    const int lane = tid & 31;
    const int wid = tid >> 5;
    const int wm = wid & 3;        // 0..3 : M warp (32 rows)
    const int wn = wid >> 2;       // 0..1 : N warp (64 cols)
    const int lr = lane >> 2;      // 0..7
    const int lc = lane & 3;       // 0..3

    // cooperative load mapping: 128 rows x 8 float4 cols; 4 f4 per thread
    const int ldrow = tid >> 1;              // 0..127
    const int ldc4a = (tid & 1) * 16;        // 0 or 16 (float index, 4 f4 apart)

    float acc[2][8][4] = {};

    // prefetch chunk 0
    float4 pa[4], pb[4];
    #pragma unroll
    for (int i = 0; i < 4; i++) {
        pa[i] = *(const float4*)&x[(size_t)(m0 + ldrow) * EE + ldc4a + i * 4];
        pb[i] = *(const float4*)&W[(size_t)(n0 + ldrow) * EE + ldc4a + i * 4];
    }

    #pragma unroll 1
    for (int kc = 0; kc < EE / 32; kc++) {
        // store prefetched chunk (tf32-rounded)
        #pragma unroll
        for (int i = 0; i < 4; i++) {
            float4 a = pa[i], b = pb[i];
            a.x = to_tf32(a.x); a.y = to_tf32(a.y); a.z = to_tf32(a.z); a.w = to_tf32(a.w);
            b.x = to_tf32(b.x); b.y = to_tf32(b.y); b.z = to_tf32(b.z); b.w = to_tf32(b.w);
            *(float4*)&As[ldrow * GPITCH + ldc4a + i * 4] = a;
            *(float4*)&Bs[ldrow * GPITCH + ldc4a + i * 4] = b;
        }
        __syncthreads();

        if (kc + 1 < EE / 32) {
            const int k0 = (kc + 1) * 32;
            #pragma unroll
            for (int i = 0; i < 4; i++) {
                pa[i] = *(const float4*)&x[(size_t)(m0 + ldrow) * EE + k0 + ldc4a + i * 4];
                pb[i] = *(const float4*)&W[(size_t)(n0 + ldrow) * EE + k0 + ldc4a + i * 4];
            }
        }

        #pragma unroll
        for (int kk = 0; kk < 32; kk += 8) {
            uint32_t a[2][4];
            #pragma unroll
            for (int mt = 0; mt < 2; mt++) {
                const int r = wm * 32 + mt * 16 + lr;
                a[mt][0] = __float_as_uint(As[r * GPITCH + kk + lc]);
                a[mt][1] = __float_as_uint(As[(r + 8) * GPITCH + kk + lc]);
                a[mt][2] = __float_as_uint(As[r * GPITCH + kk + lc + 4]);
                a[mt][3] = __float_as_uint(As[(r + 8) * GPITCH + kk + lc + 4]);
            }
            #pragma unroll
            for (int j = 0; j < 8; j++) {
                const int nc = wn * 64 + j * 8 + lr;
                uint32_t b0 = __float_as_uint(Bs[nc * GPITCH + kk + lc]);
                uint32_t b1 = __float_as_uint(Bs[nc * GPITCH + kk + lc + 4]);
                mma_tf32(acc[0][j], a[0][0], a[0][1], a[0][2], a[0][3], b0, b1);
                mma_tf32(acc[1][j], a[1][0], a[1][1], a[1][2], a[1][3], b0, b1);
            }
        }
        __syncthreads();
    }

    // Epilogue: add bias, scatter to [B,H,T,D]
    #pragma unroll
    for (int mt = 0; mt < 2; mt++) {
        #pragma unroll
        for (int j = 0; j < 8; j++) {
            const int N = n0 + wn * 64 + j * 8 + 2 * lc;
            const int h = N >> 6, d = N & 63;
            const float b0 = __ldg(&bias[N]), b1 = __ldg(&bias[N + 1]);
            #pragma unroll
            for (int half = 0; half < 2; half++) {
                const int M = m0 + wm * 32 + mt * 16 + lr + half * 8;
                const int bb = M >> 11, t = M & (TT - 1);
                float2 o;
                o.x = acc[mt][j][half * 2 + 0] + b0;
                o.y = acc[mt][j][half * 2 + 1] + b1;
                *(float2*)&dst[(((size_t)(bb * NH + h) * TT) + t) * DD + d] = o;
            }
        }
    }
}

// ===========================================================================
// Flash attention, prefix-causal band (key j valid iff j <= i + SRC).
// One block = (b, h, 64-query tile). 128 threads (4 warps); warp = 16 rows.
// S and P@V via tf32 mma.sync; online softmax in registers (quad shuffles).
// ===========================================================================
#define QP 68          // Qs/Ks/Ps pitch (4 mod 32 -> conflict-free row frags)
#define VP 72          // Vs pitch (8 mod 32 -> conflict-free column frags)
#define SM_QS 0
#define SM_KS (64 * QP)
#define SM_PS (2 * 64 * QP)
#define SM_VS (3 * 64 * QP)
#define ATTN_SMEM_FLOATS (3 * 64 * QP + 64 * VP)   // 17664 floats = 70656 B

__global__ __launch_bounds__(128) void attn_kernel(float* __restrict__ out)
{
    extern __shared__ float sm[];
    float* Qs = sm + SM_QS;
    float* Ks = sm + SM_KS;
    float* Ps = sm + SM_PS;
    float* Vs = sm + SM_VS;

    const int qtile = gridDim.x - 1 - blockIdx.x;  // heavy tiles first
    const int h = blockIdx.y;
    const int b = blockIdx.z;
    const int qs = qtile * 64;

    const float* __restrict__ Qb = g_q + (size_t)(b * NH + h) * TT * DD;
    const float* __restrict__ Kb = g_k + (size_t)(b * NH + h) * TT * DD;
    const float* __restrict__ Vb = g_v + (size_t)(b * NH + h) * TT * DD;

    const int tid = threadIdx.x;
    const int lane = tid & 31;
    const int w = tid >> 5;        // warp id: rows 16w..16w+15
    const int lr = lane >> 2;      // 0..7
    const int lc = lane & 3;       // 0..3

    // cooperative load mapping: 64 rows x 64 cols; each thread 32 floats
    const int ldrow = tid >> 1;             // 0..63
    const int ldc0 = (tid & 1) * 32;        // 0 or 32

    // ---- load Q tile (scaled by 1/8, tf32) ----
    #pragma unroll
    for (int i = 0; i < 8; i++) {
        float4 v = *(const float4*)&Qb[(size_t)(qs + ldrow) * DD + ldc0 + i * 4];
        v.x = to_tf32(v.x * 0.125f); v.y = to_tf32(v.y * 0.125f);
        v.z = to_tf32(v.z * 0.125f); v.w = to_tf32(v.w * 0.125f);
        *(float4*)&Qs[ldrow * QP + ldc0 + i * 4] = v;
    }
    __syncthreads();

    // hoist Q fragments (constant across KV loop): 8 ksteps x 4 regs
    uint32_t qa[8][4];
    {
        const int r = w * 16 + lr;
        #pragma unroll
        for (int ks8 = 0; ks8 < 8; ks8++) {
            const int kk = ks8 * 8;
            qa[ks8][0] = __float_as_uint(Qs[r * QP + kk + lc]);
            qa[ks8][1] = __float_as_uint(Qs[(r + 8) * QP + kk + lc]);
            qa[ks8][2] = __float_as_uint(Qs[r * QP + kk + lc + 4]);
            qa[ks8][3] = __float_as_uint(Qs[(r + 8) * QP + kk + lc + 4]);
        }
    }

    float o[8][4] = {};
    float m_lo = -1e30f, m_hi = -1e30f, l_lo = 0.0f, l_hi = 0.0f;

    const int ntiles = min(TT / 64, qtile + 3);

    #pragma unroll 1
    for (int jt = 0; jt < ntiles; jt++) {
        const int kst = jt * 64;
        __syncthreads();   // previous-iteration Ks/Vs reads complete

        // ---- load K, V tiles (tf32) ----
        #pragma unroll
        for (int i = 0; i < 8; i++) {
            float4 kv = *(const float4*)&Kb[(size_t)(kst + ldrow) * DD + ldc0 + i * 4];
            kv.x = to_tf32(kv.x); kv.y = to_tf32(kv.y);
            kv.z = to_tf32(kv.z); kv.w = to_tf32(kv.w);
            *(float4*)&Ks[ldrow * QP + ldc0 + i * 4] = kv;
            float4 vv = *(const float4*)&Vb[(size_t)(kst + ldrow) * DD + ldc0 + i * 4];
            vv.x = to_tf32(vv.x); vv.y = to_tf32(vv.y);
            vv.z = to_tf32(vv.z); vv.w = to_tf32(vv.w);
            *(float4*)&Vs[ldrow * VP + ldc0 + i * 4] = vv;
        }
        __syncthreads();

        // ---- S = Q @ K^T ----
        float s[8][4] = {};
        #pragma unroll
        for (int ks8 = 0; ks8 < 8; ks8++) {
            const int kk = ks8 * 8;
            #pragma unroll
            for (int j = 0; j < 8; j++) {
                const int key = j * 8 + lr;
                uint32_t b0 = __float_as_uint(Ks[key * QP + kk + lc]);
                uint32_t b1 = __float_as_uint(Ks[key * QP + kk + lc + 4]);
                mma_tf32(s[j], qa[ks8][0], qa[ks8][1], qa[ks8][2], qa[ks8][3], b0, b1);
            }
        }

        // ---- mask (last band tile only) ----
        if ((kst + 63) > (qs + SRC)) {
            const int rlo = qs + w * 16 + lr;
            #pragma unroll
            for (int j = 0; j < 8; j++) {
                const int c0 = kst + j * 8 + 2 * lc;
                if (c0     > rlo + SRC)     s[j][0] = -1e30f;
                if (c0 + 1 > rlo + SRC)     s[j][1] = -1e30f;
                if (c0     > rlo + 8 + SRC) s[j][2] = -1e30f;
                if (c0 + 1 > rlo + 8 + SRC) s[j][3] = -1e30f;
            }
        }

        // ---- online softmax (rows r=lane>>2 and r+8; quad shuffles) ----
        float mx_lo = -1e30f, mx_hi = -1e30f;
        #pragma unroll
        for (int j = 0; j < 8; j++) {
            mx_lo = fmaxf(mx_lo, fmaxf(s[j][0], s[j][1]));
            mx_hi = fmaxf(mx_hi, fmaxf(s[j][2], s[j][3]));
        }
        #pragma unroll
        for (int off = 1; off <= 2; off <<= 1) {
            mx_lo = fmaxf(mx_lo, __shfl_xor_sync(0xffffffffu, mx_lo, off));
            mx_hi = fmaxf(mx_hi, __shfl_xor_sync(0xffffffffu, mx_hi, off));
        }
        const float mn_lo = fmaxf(m_lo, mx_lo);
        const float mn_hi = fmaxf(m_hi, mx_hi);
        const float al_lo = __expf(m_lo - mn_lo);
        const float al_hi = __expf(m_hi - mn_hi);
        m_lo = mn_lo; m_hi = mn_hi;

        float sum_lo = 0.0f, sum_hi = 0.0f;
        const int prow = w * 16 + lr;
        #pragma unroll
        for (int j = 0; j < 8; j++) {
            float p0 = __expf(s[j][0] - mn_lo);
            float p1 = __expf(s[j][1] - mn_lo);
            float p2 = __expf(s[j][2] - mn_hi);
            float p3 = __expf(s[j][3] - mn_hi);
            sum_lo += p0 + p1;
            sum_hi += p2 + p3;
            float2 vlo = make_float2(to_tf32(p0), to_tf32(p1));
            float2 vhi = make_float2(to_tf32(p2), to_tf32(p3));
            *(float2*)&Ps[prow * QP + j * 8 + 2 * lc] = vlo;
            *(float2*)&Ps[(prow + 8) * QP + j * 8 + 2 * lc] = vhi;
            o[j][0] *= al_lo; o[j][1] *= al_lo;
            o[j][2] *= al_hi; o[j][3] *= al_hi;
        }
        #pragma unroll
        for (int off = 1; off <= 2; off <<= 1) {
            sum_lo += __shfl_xor_sync(0xffffffffu, sum_lo, off);
            sum_hi += __shfl_xor_sync(0xffffffffu, sum_hi, off);
        }
        l_lo = l_lo * al_lo + sum_lo;
        l_hi = l_hi * al_hi + sum_hi;
        __syncwarp();   // Ps chunk (warp-private rows) visible within warp

        // ---- O += P @ V ----
        #pragma unroll
        for (int ks8 = 0; ks8 < 8; ks8++) {
            const int k0 = ks8 * 8;
            uint32_t a0 = __float_as_uint(Ps[prow * QP + k0 + lc]);
            uint32_t a1 = __float_as_uint(Ps[(prow + 8) * QP + k0 + lc]);
            uint32_t a2 = __float_as_uint(Ps[prow * QP + k0 + lc + 4]);
            uint32_t a3 = __float_as_uint(Ps[(prow + 8) * QP + k0 + lc + 4]);
            #pragma unroll
            for (int j = 0; j < 8; j++) {
                uint32_t b0 = __float_as_uint(Vs[(k0 + lc) * VP + j * 8 + lr]);
                uint32_t b1 = __float_as_uint(Vs[(k0 + lc + 4) * VP + j * 8 + lr]);
                mma_tf32(o[j], a0, a1, a2, a3, b0, b1);
            }
        }
    }

    // ---- finalize: scale by 1/l, write out ----
    const float li_lo = 1.0f / l_lo;
    const float li_hi = 1.0f / l_hi;
    const int t_lo = qs + w * 16 + lr;
    #pragma unroll
    for (int j = 0; j < 8; j++) {
        const int d = j * 8 + 2 * lc;
        float2 v0 = make_float2(o[j][0] * li_lo, o[j][1] * li_lo);
        float2 v1 = make_float2(o[j][2] * li_hi, o[j][3] * li_hi);
        *(float2*)&out[((size_t)(b * TT + t_lo)) * EE + h * DD + d] = v0;
        *(float2*)&out[((size_t)(b * TT + t_lo + 8)) * EE + h * DD + d] = v1;
    }
}

// ---------------------------------------------------------------------------
extern "C" void kernel_launch(void* const* d_in, const int* in_sizes, int n_in,
                              void* d_out, int out_size)
{
    (void)in_sizes; (void)n_in; (void)out_size;
    const float* x  = (const float*)d_in[0];
    const float* Wq = (const float*)d_in[1];
    const float* bq = (const float*)d_in[2];
    const float* Wk = (const float*)d_in[3];
    const float* bk = (const float*)d_in[4];
    const float* Wv = (const float*)d_in[5];
    const float* bv = (const float*)d_in[6];
    float* out = (float*)d_out;

    cudaFuncSetAttribute(attn_kernel,
                         cudaFuncAttributeMaxDynamicSharedMemorySize,
                         (int)(ATTN_SMEM_FLOATS * sizeof(float)));

    dim3 ggrid(EE / 128, (BB * TT) / 128, 3);   // (8, 32, 3)
    qkv_gemm_tc<<<ggrid, 256>>>(x, Wq, bq, Wk, bk, Wv, bv);

    dim3 agrid(TT / 64, NH, BB);
    attn_kernel<<<agrid, 128, ATTN_SMEM_FLOATS * sizeof(float)>>>(out);
}

// round 6
// speedup vs baseline: 3.0298x; 1.2664x over previous
#include <cuda_runtime.h>
#include <math.h>
#include <cstdint>

#define BB 2
#define NH 16
#define TT 2048
#define DD 64
#define EE 1024
#define SRC 128

// Scratch for projected Q/K/V in [B, H, T, D] layout (no cudaMalloc allowed).
__device__ float g_q[BB * NH * TT * DD];
__device__ float g_k[BB * NH * TT * DD];
__device__ float g_v[BB * NH * TT * DD];

__device__ __forceinline__ float to_tf32(float f) {
    float r;
    asm("cvt.rna.tf32.f32 %0, %1;" : "=f"(r) : "f"(f));
    return r;
}

// D += A(16x8) * B(8x8), tf32 inputs (as b32 regs), fp32 accum.
__device__ __forceinline__ void mma_tf32(
    float* d, uint32_t a0, uint32_t a1, uint32_t a2, uint32_t a3,
    uint32_t b0, uint32_t b1)
{
    asm volatile(
        "mma.sync.aligned.m16n8k8.row.col.f32.tf32.tf32.f32 "
        "{%0,%1,%2,%3}, {%4,%5,%6,%7}, {%8,%9}, {%0,%1,%2,%3};"
        : "+f"(d[0]), "+f"(d[1]), "+f"(d[2]), "+f"(d[3])
        : "r"(a0), "r"(a1), "r"(a2), "r"(a3), "r"(b0), "r"(b1));
}

// ===========================================================================
// QKV projection: y = x @ W^T + b, scattered into [B,H,T,D].  tf32 mma.sync.
// Block tile 128x128, 256 threads (8 warps as 4Mx2N; warp tile 32x64).
// K chunks of 32 floats staged in smem (pitch 36 -> conflict-free frags).
// grid = (8, 32, 3)
// ===========================================================================
#define GPITCH 36

__global__ __launch_bounds__(256) void qkv_gemm_tc(
    const float* __restrict__ x,
    const float* __restrict__ Wq, const float* __restrict__ bq,
    const float* __restrict__ Wk, const float* __restrict__ bk,
    const float* __restrict__ Wv, const float* __restrict__ bv)
{
    __shared__ float As[128 * GPITCH];
    __shared__ float Bs[128 * GPITCH];

    const int z = blockIdx.z;
    const float* __restrict__ W    = (z == 0) ? Wq : (z == 1) ? Wk : Wv;
    const float* __restrict__ bias = (z == 0) ? bq : (z == 1) ? bk : bv;
    float* __restrict__ dst        = (z == 0) ? g_q : (z == 1) ? g_k : g_v;

    const int m0 = blockIdx.y * 128;
    const int n0 = blockIdx.x * 128;
    const int tid = threadIdx.x;
    const int lane = tid & 31;
    const int wid = tid >> 5;
    const int wm = wid & 3;        // 0..3 : M warp (32 rows)
    const int wn = wid >> 2;       // 0..1 : N warp (64 cols)
    const int lr = lane >> 2;      // 0..7
    const int lc = lane & 3;       // 0..3

    // cooperative load mapping: 128 rows x 8 float4 cols; 4 f4 per thread
    const int ldrow = tid >> 1;              // 0..127
    const int ldc4a = (tid & 1) * 16;        // 0 or 16 (float index, 4 f4 apart)

    float acc[2][8][4] = {};

    // prefetch chunk 0
    float4 pa[4], pb[4];
    #pragma unroll
    for (int i = 0; i < 4; i++) {
        pa[i] = *(const float4*)&x[(size_t)(m0 + ldrow) * EE + ldc4a + i * 4];
        pb[i] = *(const float4*)&W[(size_t)(n0 + ldrow) * EE + ldc4a + i * 4];
    }

    #pragma unroll 1
    for (int kc = 0; kc < EE / 32; kc++) {
        // store prefetched chunk (tf32-rounded)
        #pragma unroll
        for (int i = 0; i < 4; i++) {
            float4 a = pa[i], b = pb[i];
            a.x = to_tf32(a.x); a.y = to_tf32(a.y); a.z = to_tf32(a.z); a.w = to_tf32(a.w);
            b.x = to_tf32(b.x); b.y = to_tf32(b.y); b.z = to_tf32(b.z); b.w = to_tf32(b.w);
            *(float4*)&As[ldrow * GPITCH + ldc4a + i * 4] = a;
            *(float4*)&Bs[ldrow * GPITCH + ldc4a + i * 4] = b;
        }
        __syncthreads();

        if (kc + 1 < EE / 32) {
            const int k0 = (kc + 1) * 32;
            #pragma unroll
            for (int i = 0; i < 4; i++) {
                pa[i] = *(const float4*)&x[(size_t)(m0 + ldrow) * EE + k0 + ldc4a + i * 4];
                pb[i] = *(const float4*)&W[(size_t)(n0 + ldrow) * EE + k0 + ldc4a + i * 4];
            }
        }

        #pragma unroll
        for (int kk = 0; kk < 32; kk += 8) {
            uint32_t a[2][4];
            #pragma unroll
            for (int mt = 0; mt < 2; mt++) {
                const int r = wm * 32 + mt * 16 + lr;
                a[mt][0] = __float_as_uint(As[r * GPITCH + kk + lc]);
                a[mt][1] = __float_as_uint(As[(r + 8) * GPITCH + kk + lc]);
                a[mt][2] = __float_as_uint(As[r * GPITCH + kk + lc + 4]);
                a[mt][3] = __float_as_uint(As[(r + 8) * GPITCH + kk + lc + 4]);
            }
            #pragma unroll
            for (int j = 0; j < 8; j++) {
                const int nc = wn * 64 + j * 8 + lr;
                uint32_t b0 = __float_as_uint(Bs[nc * GPITCH + kk + lc]);
                uint32_t b1 = __float_as_uint(Bs[nc * GPITCH + kk + lc + 4]);
                mma_tf32(acc[0][j], a[0][0], a[0][1], a[0][2], a[0][3], b0, b1);
                mma_tf32(acc[1][j], a[1][0], a[1][1], a[1][2], a[1][3], b0, b1);
            }
        }
        __syncthreads();
    }

    // Epilogue: add bias, scatter to [B,H,T,D]
    #pragma unroll
    for (int mt = 0; mt < 2; mt++) {
        #pragma unroll
        for (int j = 0; j < 8; j++) {
            const int N = n0 + wn * 64 + j * 8 + 2 * lc;
            const int h = N >> 6, d = N & 63;
            const float b0 = __ldg(&bias[N]), b1 = __ldg(&bias[N + 1]);
            #pragma unroll
            for (int half = 0; half < 2; half++) {
                const int M = m0 + wm * 32 + mt * 16 + lr + half * 8;
                const int bb = M >> 11, t = M & (TT - 1);
                float2 o;
                o.x = acc[mt][j][half * 2 + 0] + b0;
                o.y = acc[mt][j][half * 2 + 1] + b1;
                *(float2*)&dst[(((size_t)(bb * NH + h) * TT) + t) * DD + d] = o;
            }
        }
    }
}

// ===========================================================================
// Flash attention, prefix-causal band (key j valid iff j <= i + SRC).
// One block = (b, h, 128-query tile). 256 threads (8 warps); warp = 16 rows.
// S and P@V via tf32 mma.sync; online softmax in registers (quad shuffles).
// Ps overlays the Q staging buffer (Q fragments hoisted to registers first).
// ===========================================================================
#define QP 68          // Qs/Ks/Ps pitch (4 mod 32 -> conflict-free row frags)
#define VP 72          // Vs pitch (8 mod 32 -> conflict-free column frags)
#define SM_QS 0        // 128 x QP floats, reused as Ps after Q-frag hoist
#define SM_KS (128 * QP)
#define SM_VS (128 * QP + 64 * QP)
#define ATTN_SMEM_FLOATS (128 * QP + 64 * QP + 64 * VP)   // 17664 floats = 70656 B

__global__ __launch_bounds__(256) void attn_kernel(float* __restrict__ out)
{
    extern __shared__ float sm[];
    float* Qs = sm + SM_QS;      // staging; becomes Ps inside the loop
    float* Ps = sm + SM_QS;
    float* Ks = sm + SM_KS;
    float* Vs = sm + SM_VS;

    const int qtile = gridDim.x - 1 - blockIdx.x;  // heavy tiles first
    const int h = blockIdx.y;
    const int b = blockIdx.z;
    const int qs = qtile * 128;

    const float* __restrict__ Qb = g_q + (size_t)(b * NH + h) * TT * DD;
    const float* __restrict__ Kb = g_k + (size_t)(b * NH + h) * TT * DD;
    const float* __restrict__ Vb = g_v + (size_t)(b * NH + h) * TT * DD;

    const int tid = threadIdx.x;
    const int lane = tid & 31;
    const int w = tid >> 5;        // warp id 0..7: rows 16w..16w+15
    const int lr = lane >> 2;      // 0..7
    const int lc = lane & 3;       // 0..3

    // Q cooperative load: 128 rows x 64 cols; each thread 32 floats
    const int qldrow = tid >> 1;            // 0..127
    const int qldc0 = (tid & 1) * 32;       // 0 or 32
    // K/V cooperative load: 64 rows x 64 cols; each thread 16 floats
    const int kldrow = tid >> 2;            // 0..63
    const int kldc0 = (tid & 3) * 16;       // 0,16,32,48

    // ---- load Q tile (scaled by 1/8, tf32) ----
    #pragma unroll
    for (int i = 0; i < 8; i++) {
        float4 v = *(const float4*)&Qb[(size_t)(qs + qldrow) * DD + qldc0 + i * 4];
        v.x = to_tf32(v.x * 0.125f); v.y = to_tf32(v.y * 0.125f);
        v.z = to_tf32(v.z * 0.125f); v.w = to_tf32(v.w * 0.125f);
        *(float4*)&Qs[qldrow * QP + qldc0 + i * 4] = v;
    }
    __syncthreads();

    // hoist Q fragments (constant across KV loop): 8 ksteps x 4 regs
    uint32_t qa[8][4];
    {
        const int r = w * 16 + lr;
        #pragma unroll
        for (int ks8 = 0; ks8 < 8; ks8++) {
            const int kk = ks8 * 8;
            qa[ks8][0] = __float_as_uint(Qs[r * QP + kk + lc]);
            qa[ks8][1] = __float_as_uint(Qs[(r + 8) * QP + kk + lc]);
            qa[ks8][2] = __float_as_uint(Qs[r * QP + kk + lc + 4]);
            qa[ks8][3] = __float_as_uint(Qs[(r + 8) * QP + kk + lc + 4]);
        }
    }

    float o[8][4] = {};
    float m_lo = -1e30f, m_hi = -1e30f, l_lo = 0.0f, l_hi = 0.0f;

    const int ntiles = min(TT / 64, qtile * 2 + 4);

    #pragma unroll 1
    for (int jt = 0; jt < ntiles; jt++) {
        const int kst = jt * 64;
        __syncthreads();   // prev-iter Ks/Vs/Ps reads complete (iter 0: Q hoists done)

        // ---- load K, V tiles (tf32) ----
        #pragma unroll
        for (int i = 0; i < 4; i++) {
            float4 kv = *(const float4*)&Kb[(size_t)(kst + kldrow) * DD + kldc0 + i * 4];
            kv.x = to_tf32(kv.x); kv.y = to_tf32(kv.y);
            kv.z = to_tf32(kv.z); kv.w = to_tf32(kv.w);
            *(float4*)&Ks[kldrow * QP + kldc0 + i * 4] = kv;
            float4 vv = *(const float4*)&Vb[(size_t)(kst + kldrow) * DD + kldc0 + i * 4];
            vv.x = to_tf32(vv.x); vv.y = to_tf32(vv.y);
            vv.z = to_tf32(vv.z); vv.w = to_tf32(vv.w);
            *(float4*)&Vs[kldrow * VP + kldc0 + i * 4] = vv;
        }
        __syncthreads();

        // ---- S = Q @ K^T ----
        float s[8][4] = {};
        #pragma unroll
        for (int ks8 = 0; ks8 < 8; ks8++) {
            const int kk = ks8 * 8;
            #pragma unroll
            for (int j = 0; j < 8; j++) {
                const int key = j * 8 + lr;
                uint32_t b0 = __float_as_uint(Ks[key * QP + kk + lc]);
                uint32_t b1 = __float_as_uint(Ks[key * QP + kk + lc + 4]);
                mma_tf32(s[j], qa[ks8][0], qa[ks8][1], qa[ks8][2], qa[ks8][3], b0, b1);
            }
        }

        // ---- mask (partially-banded tiles only) ----
        if ((kst + 63) > (qs + SRC)) {
            const int rlo = qs + w * 16 + lr;
            #pragma unroll
            for (int j = 0; j < 8; j++) {
                const int c0 = kst + j * 8 + 2 * lc;
                if (c0     > rlo + SRC)     s[j][0] = -1e30f;
                if (c0 + 1 > rlo + SRC)     s[j][1] = -1e30f;
                if (c0     > rlo + 8 + SRC) s[j][2] = -1e30f;
                if (c0 + 1 > rlo + 8 + SRC) s[j][3] = -1e30f;
            }
        }

        // ---- online softmax (rows r=lane>>2 and r+8; quad shuffles) ----
        float mx_lo = -1e30f, mx_hi = -1e30f;
        #pragma unroll
        for (int j = 0; j < 8; j++) {
            mx_lo = fmaxf(mx_lo, fmaxf(s[j][0], s[j][1]));
            mx_hi = fmaxf(mx_hi, fmaxf(s[j][2], s[j][3]));
        }
        #pragma unroll
        for (int off = 1; off <= 2; off <<= 1) {
            mx_lo = fmaxf(mx_lo, __shfl_xor_sync(0xffffffffu, mx_lo, off));
            mx_hi = fmaxf(mx_hi, __shfl_xor_sync(0xffffffffu, mx_hi, off));
        }
        const float mn_lo = fmaxf(m_lo, mx_lo);
        const float mn_hi = fmaxf(m_hi, mx_hi);
        const float al_lo = __expf(m_lo - mn_lo);
        const float al_hi = __expf(m_hi - mn_hi);
        m_lo = mn_lo; m_hi = mn_hi;

        float sum_lo = 0.0f, sum_hi = 0.0f;
        const int prow = w * 16 + lr;
        #pragma unroll
        for (int j = 0; j < 8; j++) {
            float p0 = __expf(s[j][0] - mn_lo);
            float p1 = __expf(s[j][1] - mn_lo);
            float p2 = __expf(s[j][2] - mn_hi);
            float p3 = __expf(s[j][3] - mn_hi);
            sum_lo += p0 + p1;
            sum_hi += p2 + p3;
            float2 vlo = make_float2(to_tf32(p0), to_tf32(p1));
            float2 vhi = make_float2(to_tf32(p2), to_tf32(p3));
            *(float2*)&Ps[prow * QP + j * 8 + 2 * lc] = vlo;
            *(float2*)&Ps[(prow + 8) * QP + j * 8 + 2 * lc] = vhi;
            o[j][0] *= al_lo; o[j][1] *= al_lo;
            o[j][2] *= al_hi; o[j][3] *= al_hi;
        }
        #pragma unroll
        for (int off = 1; off <= 2; off <<= 1) {
            sum_lo += __shfl_xor_sync(0xffffffffu, sum_lo, off);
            sum_hi += __shfl_xor_sync(0xffffffffu, sum_hi, off);
        }
        l_lo = l_lo * al_lo + sum_lo;
        l_hi = l_hi * al_hi + sum_hi;
        __syncwarp();   // Ps rows are warp-private; make stores visible in-warp

        // ---- O += P @ V ----
        #pragma unroll
        for (int ks8 = 0; ks8 < 8; ks8++) {
            const int k0 = ks8 * 8;
            uint32_t a0 = __float_as_uint(Ps[prow * QP + k0 + lc]);
            uint32_t a1 = __float_as_uint(Ps[(prow + 8) * QP + k0 + lc]);
            uint32_t a2 = __float_as_uint(Ps[prow * QP + k0 + lc + 4]);
            uint32_t a3 = __float_as_uint(Ps[(prow + 8) * QP + k0 + lc + 4]);
            #pragma unroll
            for (int j = 0; j < 8; j++) {
                uint32_t b0 = __float_as_uint(Vs[(k0 + lc) * VP + j * 8 + lr]);
                uint32_t b1 = __float_as_uint(Vs[(k0 + lc + 4) * VP + j * 8 + lr]);
                mma_tf32(o[j], a0, a1, a2, a3, b0, b1);
            }
        }
    }

    // ---- finalize: scale by 1/l, write out ----
    const float li_lo = 1.0f / l_lo;
    const float li_hi = 1.0f / l_hi;
    const int t_lo = qs + w * 16 + lr;
    #pragma unroll
    for (int j = 0; j < 8; j++) {
        const int d = j * 8 + 2 * lc;
        float2 v0 = make_float2(o[j][0] * li_lo, o[j][1] * li_lo);
        float2 v1 = make_float2(o[j][2] * li_hi, o[j][3] * li_hi);
        *(float2*)&out[((size_t)(b * TT + t_lo)) * EE + h * DD + d] = v0;
        *(float2*)&out[((size_t)(b * TT + t_lo + 8)) * EE + h * DD + d] = v1;
    }
}

// ---------------------------------------------------------------------------
extern "C" void kernel_launch(void* const* d_in, const int* in_sizes, int n_in,
                              void* d_out, int out_size)
{
    (void)in_sizes; (void)n_in; (void)out_size;
    const float* x  = (const float*)d_in[0];
    const float* Wq = (const float*)d_in[1];
    const float* bq = (const float*)d_in[2];
    const float* Wk = (const float*)d_in[3];
    const float* bk = (const float*)d_in[4];
    const float* Wv = (const float*)d_in[5];
    const float* bv = (const float*)d_in[6];
    float* out = (float*)d_out;

    cudaFuncSetAttribute(attn_kernel,
                         cudaFuncAttributeMaxDynamicSharedMemorySize,
                         (int)(ATTN_SMEM_FLOATS * sizeof(float)));

    dim3 ggrid(EE / 128, (BB * TT) / 128, 3);   // (8, 32, 3)
    qkv_gemm_tc<<<ggrid, 256>>>(x, Wq, bq, Wk, bk, Wv, bv);

    dim3 agrid(TT / 128, NH, BB);               // (16, 16, 2)
    attn_kernel<<<agrid, 256, ATTN_SMEM_FLOATS * sizeof(float)>>>(out);
}